// round 10
// baseline (speedup 1.0000x reference)
#include <cuda_runtime.h>
#include <math.h>

#define C_IN   64
#define FD     8
#define OUTC   9
#define KW     5
#define HEIGHT 4096
#define BATCH  32
#define NTOK   (BATCH * HEIGHT)      // 131072 tokens (b,h)
#define HALF   36
#define MIN_EIG 0.001f
#define NSWEEP 4

// SoA scratch: sigma[e][token]
__device__ float g_sigma[HALF * NTOK];

typedef unsigned long long ull;

__device__ __forceinline__ ull pk(float lo, float hi) {
    ull r; asm("mov.b64 %0, {%1, %2};" : "=l"(r) : "f"(lo), "f"(hi)); return r;
}
__device__ __forceinline__ void upk(ull v, float& lo, float& hi) {
    asm("mov.b64 {%0, %1}, %2;" : "=f"(lo), "=f"(hi) : "l"(v));
}
__device__ __forceinline__ ull fma2(ull a, ull b, ull c) {
    ull d; asm("fma.rn.f32x2 %0, %1, %2, %3;" : "=l"(d) : "l"(a), "l"(b), "l"(c)); return d;
}
__device__ __forceinline__ ull mul2(ull a, ull b) {
    ull d; asm("mul.rn.f32x2 %0, %1, %2;" : "=l"(d) : "l"(a), "l"(b)); return d;
}
__device__ __forceinline__ float softplus(float v) {
    return v > 20.0f ? v : log1pf(expf(v));
}

// ---------------------------------------------------------------------------
// Kernel 1: Winograd F(4,5) p-conv + 1x1 conv (loc), warp-pair output split.
//   even warp: p-conv outputs o=0..4   (20 ULL accumulators)
//   odd  warp: p-conv outputs o=5..8 + packed loc (20 ULL accumulators)
// Both warps of a pair process the same 32 tokens.
// Winograd g-side constants computed in the block prologue (no wprep launch).
// Points a = {0, +1, -1, +2, -2, +1/2, -1/2} + infinity; exact 1/N_i folded.
// ---------------------------------------------------------------------------
__global__ void __launch_bounds__(256, 3) conv_kernel(
    const float* __restrict__ x,   // [B, C_IN, H, FD]
    const float* __restrict__ wn,  // [C_IN]
    const float* __restrict__ bn,  // [1]
    const float* __restrict__ wp,  // [OUTC, C_IN, 1, KW]
    const float* __restrict__ bp,  // [OUTC]
    float* __restrict__ out_loc)   // [NTOK, FD]
{
    __shared__ ull  s_gt[C_IN * OUTC * 4];   // [(c*9+o)*4] packed (G~ pairs)
    __shared__ ull  s_wn2[C_IN];
    __shared__ float s_b[OUTC + 1];

    const int t = threadIdx.x;

    // ---- in-block weight transform (replaces wprep kernel) ----
    for (int i = t; i < OUTC * C_IN; i += 256) {
        const int o = i / C_IN, c = i - o * C_IN;
        const float* g = wp + i * KW;
        const float g0 = g[0], g1 = g[1], g2 = g[2], g3 = g[3], g4 = g[4];
        // g(a) by Horner at each point
        #define GEV(a) fmaf(fmaf(fmaf(fmaf(g4,(a),g3),(a),g2),(a),g1),(a),g0)
        const float Gt0 = GEV(0.0f)  * -1.0f;
        const float Gt1 = GEV(1.0f)  * -0.222222222222f;
        const float Gt2 = GEV(-1.0f) * -0.222222222222f;
        const float Gt3 = GEV(2.0f)  *  0.011111111111f;
        const float Gt4 = GEV(-2.0f) *  0.011111111111f;
        const float Gt5 = GEV(0.5f)  *  0.711111111111f;
        const float Gt6 = GEV(-0.5f) *  0.711111111111f;
        #undef GEV
        ull* dst = s_gt + (c * OUTC + o) * 4;
        dst[0] = pk(Gt0, Gt1);
        dst[1] = pk(Gt2, Gt3);
        dst[2] = pk(Gt4, Gt5);
        dst[3] = pk(Gt6, g4);
    }
    if (t < C_IN) { float w = wn[t]; s_wn2[t] = pk(w, w); }
    if (t < OUTC) s_b[t] = bp[t];
    if (t == 0)   s_b[OUTC] = bn[0];
    __syncthreads();

    const int wid  = t >> 5;            // 0..7
    const int lane = t & 31;
    const int tok  = (blockIdx.x * 4 + (wid >> 1)) * 32 + lane;
    const int b = tok >> 12;            // H = 4096
    const int h = tok & (HEIGHT - 1);
    const float* xb = x + (size_t)b * (C_IN * HEIGHT * FD) + (size_t)h * FD;

    const bool evenw = ((wid & 1) == 0);
    const int OB = evenw ? 0 : 5;       // warp-uniform
    const int NO = evenw ? 5 : 4;

    ull acc[20];                        // even: 5 o x 4; odd: 4 o x 4 + 4 loc
#pragma unroll
    for (int e = 0; e < 20; e++) acc[e] = 0ULL;

    const float4* p0 = (const float4*)xb;
    float4 u = p0[0];
    float4 v = p0[1];

#pragma unroll 4
    for (int c = 0; c < C_IN; c++) {
        float4 nu, nv;
        if (c < C_IN - 1) {
            const float4* pn = (const float4*)(xb + (size_t)(c + 1) * (HEIGHT * FD));
            nu = pn[0]; nv = pn[1];
        }
        const float d0 = u.x, d1 = u.y, d2 = u.z, d3 = u.w;
        const float d4 = v.x, d5 = v.y, d6 = v.z, d7 = v.w;

        // Winograd data functionals
        const float E1 = fmaf(-4.25f, d4, d2 + d6);
        const float O1 = fmaf(-4.25f, d3, d1 + d5);
        const float E2 = fmaf(0.25f, d2, fmaf(-1.25f, d4, d6));
        const float O2 = fmaf(0.5f,  d1, fmaf(-2.5f,  d3, 2.0f * d5));
        const float E3 = fmaf(4.0f,  d2, fmaf(-5.0f,  d4, d6));
        const float O3 = fmaf(2.0f,  d1, fmaf(-2.5f,  d3, 0.5f * d5));
        const ull X01 = pk(fmaf(5.25f, d2 - d4, d6 - d0), E1 + O1);
        const ull X23 = pk(E1 - O1, E2 + O2);
        const ull X45 = pk(E2 - O2, E3 + O3);
        const ull X67 = pk(E3 - O3, fmaf(5.25f, d3 - d5, d7 - d1));

        const ull* gc = s_gt + c * (OUTC * 4) + OB * 4;
#pragma unroll
        for (int o = 0; o < 4; o++) {
            ulonglong2 wA = *(const ulonglong2*)(gc + o * 4);
            ulonglong2 wB = *(const ulonglong2*)(gc + o * 4 + 2);
            acc[o * 4 + 0] = fma2(X01, wA.x, acc[o * 4 + 0]);
            acc[o * 4 + 1] = fma2(X23, wA.y, acc[o * 4 + 1]);
            acc[o * 4 + 2] = fma2(X45, wB.x, acc[o * 4 + 2]);
            acc[o * 4 + 3] = fma2(X67, wB.y, acc[o * 4 + 3]);
        }
        if (evenw) {
            // 5th output channel (o = 4)
            ulonglong2 wA = *(const ulonglong2*)(gc + 16);
            ulonglong2 wB = *(const ulonglong2*)(gc + 18);
            acc[16] = fma2(X01, wA.x, acc[16]);
            acc[17] = fma2(X23, wA.y, acc[17]);
            acc[18] = fma2(X45, wB.x, acc[18]);
            acc[19] = fma2(X67, wB.y, acc[19]);
        } else {
            // packed loc: pairs (d0,d1)(d2,d3)(d4,d5)(d6,d7) x wn broadcast
            const ull wc = s_wn2[c];
            acc[16] = fma2(pk(d0, d1), wc, acc[16]);
            acc[17] = fma2(pk(d2, d3), wc, acc[17]);
            acc[18] = fma2(pk(d4, d5), wc, acc[18]);
            acc[19] = fma2(pk(d6, d7), wc, acc[19]);
        }
        u = nu; v = nv;
    }

    // ---- epilogue: A^T output transform + softplus ----
#pragma unroll
    for (int oi = 0; oi < 4; oi++) {
        const int o = OB + oi;
        float P0, P1, P2, P3, P4, P5, P6, P7;
        upk(acc[oi * 4 + 0], P0, P1);
        upk(acc[oi * 4 + 1], P2, P3);
        upk(acc[oi * 4 + 2], P4, P5);
        upk(acc[oi * 4 + 3], P6, P7);
        const float S1 = P1 + P2, D1 = P1 - P2;
        const float S2 = P3 + P4, D2 = P3 - P4;
        const float S3 = P5 + P6, D3 = P5 - P6;
        const float y0 = P0 + S1 + S2 + S3;
        const float y1 = fmaf(2.0f, D2, fmaf(0.5f,   D3, D1));
        const float y2 = fmaf(4.0f, S2, fmaf(0.25f,  S3, S1));
        const float y3 = fmaf(8.0f, D2, fmaf(0.125f, D3, D1)) + P7;
        const float be = s_b[o];
        g_sigma[(size_t)(o * 4 + 0) * NTOK + tok] = softplus(y0 + be);
        g_sigma[(size_t)(o * 4 + 1) * NTOK + tok] = softplus(y1 + be);
        g_sigma[(size_t)(o * 4 + 2) * NTOK + tok] = softplus(y2 + be);
        g_sigma[(size_t)(o * 4 + 3) * NTOK + tok] = softplus(y3 + be);
    }

    if (evenw) {
        // o = 4
        float P0, P1, P2, P3, P4, P5, P6, P7;
        upk(acc[16], P0, P1);
        upk(acc[17], P2, P3);
        upk(acc[18], P4, P5);
        upk(acc[19], P6, P7);
        const float S1 = P1 + P2, D1 = P1 - P2;
        const float S2 = P3 + P4, D2 = P3 - P4;
        const float S3 = P5 + P6, D3 = P5 - P6;
        const float y0 = P0 + S1 + S2 + S3;
        const float y1 = fmaf(2.0f, D2, fmaf(0.5f,   D3, D1));
        const float y2 = fmaf(4.0f, S2, fmaf(0.25f,  S3, S1));
        const float y3 = fmaf(8.0f, D2, fmaf(0.125f, D3, D1)) + P7;
        const float be = s_b[4];
        g_sigma[(size_t)(16) * NTOK + tok] = softplus(y0 + be);
        g_sigma[(size_t)(17) * NTOK + tok] = softplus(y1 + be);
        g_sigma[(size_t)(18) * NTOK + tok] = softplus(y2 + be);
        g_sigma[(size_t)(19) * NTOK + tok] = softplus(y3 + be);
    } else {
        // loc
        const float bnv = s_b[OUTC];
        float r[8];
#pragma unroll
        for (int j = 0; j < 4; j++) {
            float a, bb;
            upk(acc[16 + j], a, bb);
            r[2 * j]     = softplus(a + bnv);
            r[2 * j + 1] = softplus(bb + bnv);
        }
        float4* lp = (float4*)(out_loc + (size_t)tok * FD);
        lp[0] = make_float4(r[0], r[1], r[2], r[3]);
        lp[1] = make_float4(r[4], r[5], r[6], r[7]);
    }
}

// ---------------------------------------------------------------------------
// Kernel 2: batched 8x8 symmetric eigh, fixed-sweep cyclic Jacobi.
// (R5 version verbatim: best measured at 48.2 us.)
// ---------------------------------------------------------------------------
#define TI(i,j) ((i) <= (j) ? ((i)*(17-(i)))/2 + ((j)-(i)) \
                            : ((j)*(17-(j)))/2 + ((i)-(j)))
#define AT(i,j) Au[TI(i,j)]

__global__ void __launch_bounds__(128) eigh_kernel(float* __restrict__ out_pd)
{
    const int tok = blockIdx.x * 128 + threadIdx.x;

    float Au[HALF];
#pragma unroll
    for (int e = 0; e < HALF; e++) Au[e] = g_sigma[(size_t)e * NTOK + tok];

    // V packed as row-pairs: Vp[col][jp] = ( V[2jp][col], V[2jp+1][col] )
    ull Vp[8][4];
#pragma unroll
    for (int c = 0; c < 8; c++)
#pragma unroll
        for (int jp = 0; jp < 4; jp++)
            Vp[c][jp] = pk((2 * jp == c) ? 1.0f : 0.0f,
                           (2 * jp + 1 == c) ? 1.0f : 0.0f);

#pragma unroll 1
    for (int sweep = 0; sweep < NSWEEP; sweep++) {
#pragma unroll
        for (int p = 0; p < 7; p++) {
#pragma unroll
            for (int q = p + 1; q < 8; q++) {
                float apq = AT(p, q);
                float app = AT(p, p);
                float aqq = AT(q, q);
                float tau = (aqq - app);
                tau += copysignf(1e-18f, tau);          // degenerate-safe
                float r2    = fmaf(tau, tau, 4.0f * apq * apq);
                float inv_r = rsqrtf(r2);
                float c2    = fmaf(0.5f * fabsf(tau), inv_r, 0.5f); // cos^2
                float cinv  = rsqrtf(c2);
                float cc    = c2 * cinv;                            // cos
                float st    = (tau < 0.0f) ? -apq : apq;            // sign(tau)*apq
                float ss    = st * inv_r * cinv;                    // sin
                float s2c   = 2.0f * st * inv_r;                    // sin(2phi) fold

                float napp = c2 * app + (1.0f - c2) * aqq - s2c * apq;
                AT(p, p) = napp;
                AT(q, q) = (app + aqq) - napp;
                AT(p, q) = 0.0f;

#pragma unroll
                for (int j = 0; j < 8; j++) {
                    if (j == p || j == q) continue;
                    float ajp = AT(j, p), ajq = AT(j, q);
                    AT(j, p) = cc * ajp - ss * ajq;
                    AT(j, q) = ss * ajp + cc * ajq;
                }

                // packed V column rotation
                ull cc2  = pk(cc, cc);
                ull ss2  = pk(ss, ss);
                ull nss2 = pk(-ss, -ss);
#pragma unroll
                for (int jp = 0; jp < 4; jp++) {
                    ull vp = Vp[p][jp], vq = Vp[q][jp];
                    Vp[p][jp] = fma2(nss2, vq, mul2(cc2, vp));
                    Vp[q][jp] = fma2(cc2,  vq, mul2(ss2, vp));
                }
            }
        }
    }

    float V[8][8];   // V[row][col]
#pragma unroll
    for (int c = 0; c < 8; c++)
#pragma unroll
        for (int jp = 0; jp < 4; jp++)
            upk(Vp[c][jp], V[2 * jp][c], V[2 * jp + 1][c]);

    float lam[8];
#pragma unroll
    for (int k = 0; k < 8; k++) lam[k] = fmaxf(AT(k, k), MIN_EIG);

    float W[8][8];
#pragma unroll
    for (int i = 0; i < 8; i++)
#pragma unroll
        for (int k = 0; k < 8; k++) W[i][k] = V[i][k] * lam[k];

    float pd[8][8];
#pragma unroll
    for (int i = 0; i < 8; i++) {
#pragma unroll
        for (int j = i; j < 8; j++) {
            float acc = 0.0f;
#pragma unroll
            for (int k = 0; k < 8; k++) acc = fmaf(W[i][k], V[j][k], acc);
            pd[i][j] = acc; pd[j][i] = acc;
        }
    }

    float* o = out_pd + (size_t)tok * 64;
#pragma unroll
    for (int i = 0; i < 8; i++) {
        ((float4*)o)[i * 2]     = make_float4(pd[i][0], pd[i][1], pd[i][2], pd[i][3]);
        ((float4*)o)[i * 2 + 1] = make_float4(pd[i][4], pd[i][5], pd[i][6], pd[i][7]);
    }
}

// ---------------------------------------------------------------------------
extern "C" void kernel_launch(void* const* d_in, const int* in_sizes, int n_in,
                              void* d_out, int out_size)
{
    // Identify inputs by element count (robust to metadata ordering):
    // x: 67108864, w_n: 64, b_n: 1, w_p: 2880, b_p: 9
    const float* x  = nullptr;
    const float* wn = nullptr;
    const float* bn = nullptr;
    const float* wp = nullptr;
    const float* bp = nullptr;
    for (int i = 0; i < n_in; i++) {
        switch (in_sizes[i]) {
            case 64:    wn = (const float*)d_in[i]; break;
            case 1:     bn = (const float*)d_in[i]; break;
            case 2880:  wp = (const float*)d_in[i]; break;
            case 9:     bp = (const float*)d_in[i]; break;
            default:    x  = (const float*)d_in[i]; break;
        }
    }

    float* out = (float*)d_out;
    float* loc = out;                                            // [B,1,H,FD]
    float* pd  = out + ((size_t)out_size - (size_t)NTOK * 64);   // [B,1,H,8,8]

    conv_kernel<<<NTOK / 128, 256>>>(x, wn, bn, wp, bp, loc);
    eigh_kernel<<<NTOK / 128, 128>>>(pd);
}

// round 11
// speedup vs baseline: 1.2636x; 1.2636x over previous
#include <cuda_runtime.h>
#include <math.h>

#define C_IN   64
#define FD     8
#define OUTC   9
#define KW     5
#define HEIGHT 4096
#define BATCH  32
#define NTOK   (BATCH * HEIGHT)      // 131072 tokens (b,h)
#define HALF   36
#define MIN_EIG 0.001f
#define NSWEEP 4

// SoA scratch: sigma[e][token]
__device__ float g_sigma[HALF * NTOK];

typedef unsigned long long ull;

__device__ __forceinline__ ull pk(float lo, float hi) {
    ull r; asm("mov.b64 %0, {%1, %2};" : "=l"(r) : "f"(lo), "f"(hi)); return r;
}
__device__ __forceinline__ void upk(ull v, float& lo, float& hi) {
    asm("mov.b64 {%0, %1}, %2;" : "=f"(lo), "=f"(hi) : "l"(v));
}
__device__ __forceinline__ ull fma2(ull a, ull b, ull c) {
    ull d; asm("fma.rn.f32x2 %0, %1, %2, %3;" : "=l"(d) : "l"(a), "l"(b), "l"(c)); return d;
}
__device__ __forceinline__ ull mul2(ull a, ull b) {
    ull d; asm("mul.rn.f32x2 %0, %1, %2;" : "=l"(d) : "l"(a), "l"(b)); return d;
}
__device__ __forceinline__ float softplus(float v) {
    return v > 20.0f ? v : log1pf(expf(v));
}

// ---------------------------------------------------------------------------
// Conv channel-compute: FFMA2 packed over adjacent feature positions.
// (R8 version verbatim — best measured conv at 97.5 us.)
// ---------------------------------------------------------------------------
template<int OB, int OE, bool DOLOC>
__device__ __forceinline__ void conv_step(
    const float4 u, const float4 v,
    const ull* __restrict__ s_wp2,     // [o][c][k] padded to 6
    const ull* __restrict__ s_wn2,
    int c, ull* accL, ull* accP)
{
    float xv[8] = {u.x, u.y, u.z, u.w, v.x, v.y, v.z, v.w};
    ull xm[7];                          // xm[m] = (x[m], x[m+1])
#pragma unroll
    for (int m = 0; m < 7; m++) xm[m] = pk(xv[m], xv[m + 1]);

    if (DOLOC) {
        const ull w0 = s_wn2[c];
#pragma unroll
        for (int j = 0; j < FD / 2; j++) accL[j] = fma2(xm[2 * j], w0, accL[j]);
    }

#pragma unroll
    for (int o = OB; o < OE; o++) {
        const ull* wr = s_wp2 + (o * C_IN + c) * 6;
        ulonglong2 wA = *(const ulonglong2*)(wr);      // w0, w1
        ulonglong2 wB = *(const ulonglong2*)(wr + 2);  // w2, w3
        ull w4 = wr[4];
        ull w[KW] = {wA.x, wA.y, wB.x, wB.y, w4};
#pragma unroll
        for (int wq = 0; wq < 2; wq++) {
#pragma unroll
            for (int k = 0; k < KW; k++)
                accP[(o - OB) * 2 + wq] =
                    fma2(xm[2 * wq + k], w[k], accP[(o - OB) * 2 + wq]);
        }
    }
}

// Pipelined channel loop: prefetch channel c+1 while computing channel c.
template<int OB, int OE, bool DOLOC>
__device__ __forceinline__ void conv_loop(
    const float* __restrict__ xb,
    const ull* __restrict__ s_wp2,
    const ull* __restrict__ s_wn2,
    ull* accL, ull* accP)
{
    const float4* p0 = (const float4*)xb;
    float4 u = p0[0];
    float4 v = p0[1];
#pragma unroll 4
    for (int c = 0; c < C_IN - 1; c++) {
        const float4* pn = (const float4*)(xb + (size_t)(c + 1) * (HEIGHT * FD));
        float4 nu = pn[0];
        float4 nv = pn[1];
        conv_step<OB, OE, DOLOC>(u, v, s_wp2, s_wn2, c, accL, accP);
        u = nu; v = nv;
    }
    conv_step<OB, OE, DOLOC>(u, v, s_wp2, s_wn2, C_IN - 1, accL, accP);
}

// ---------------------------------------------------------------------------
// Kernel 1: fused 1x1 conv (loc) + (1,5) valid conv (sigma entries).
// Warp-pair split (uniform per warp, no divergence):
//   even warp: loc + outputs o=0..3 ; odd warp: outputs o=4..8
// Both warps of a pair process the same 32 tokens (x loads hit L1/L2).
// ---------------------------------------------------------------------------
__global__ void __launch_bounds__(256, 3) conv_kernel(
    const float* __restrict__ x,   // [B, C_IN, H, FD]
    const float* __restrict__ wn,  // [C_IN]
    const float* __restrict__ bn,  // [1]
    const float* __restrict__ wp,  // [OUTC, C_IN, 1, KW]
    const float* __restrict__ bp,  // [OUTC]
    float* __restrict__ out_loc)   // [NTOK, FD]
{
    __shared__ ull  s_wp2[OUTC * C_IN * 6];    // broadcast-packed, padded to 6
    __shared__ ull  s_wn2[C_IN];
    __shared__ float s_b[OUTC + 1];

    const int t = threadIdx.x;
    for (int i = t; i < OUTC * C_IN * KW; i += 256) {
        int oc = i / KW, k = i - oc * KW;
        float w = wp[i];
        s_wp2[oc * 6 + k] = pk(w, w);
    }
    if (t < C_IN) { float w = wn[t]; s_wn2[t] = pk(w, w); }
    if (t < OUTC) s_b[t] = bp[t];
    if (t == 0)   s_b[OUTC] = bn[0];
    __syncthreads();

    const int wid  = t >> 5;           // 0..7
    const int lane = t & 31;
    const int tok  = (blockIdx.x * 4 + (wid >> 1)) * 32 + lane;
    const int b = tok >> 12;           // H = 4096
    const int h = tok & (HEIGHT - 1);

    const float* xb = x + (size_t)b * (C_IN * HEIGHT * FD) + (size_t)h * FD;

    if ((wid & 1) == 0) {
        // ---------------- even warp: loc + o0..3 ----------------
        ull accL[FD / 2];
        ull accP[8];
#pragma unroll
        for (int j = 0; j < FD / 2; j++) accL[j] = 0ULL;
#pragma unroll
        for (int e = 0; e < 8; e++) accP[e] = 0ULL;

        conv_loop<0, 4, true>(xb, s_wp2, s_wn2, accL, accP);

        const float bnv = s_b[OUTC];
        float r[8];
#pragma unroll
        for (int j = 0; j < FD / 2; j++) {
            float a, bb;
            upk(accL[j], a, bb);
            r[2 * j]     = softplus(a + bnv);
            r[2 * j + 1] = softplus(bb + bnv);
        }
        float4* lp = (float4*)(out_loc + (size_t)tok * FD);
        lp[0] = make_float4(r[0], r[1], r[2], r[3]);
        lp[1] = make_float4(r[4], r[5], r[6], r[7]);

#pragma unroll
        for (int o = 0; o < 4; o++) {
            float be = s_b[o];
            float a, bb;
            upk(accP[o * 2], a, bb);
            g_sigma[(o * 4 + 0) * NTOK + tok] = softplus(a + be);
            g_sigma[(o * 4 + 1) * NTOK + tok] = softplus(bb + be);
            upk(accP[o * 2 + 1], a, bb);
            g_sigma[(o * 4 + 2) * NTOK + tok] = softplus(a + be);
            g_sigma[(o * 4 + 3) * NTOK + tok] = softplus(bb + be);
        }
    } else {
        // ---------------- odd warp: o4..8 ----------------
        ull accP[10];
#pragma unroll
        for (int e = 0; e < 10; e++) accP[e] = 0ULL;

        conv_loop<4, 9, false>(xb, s_wp2, s_wn2, (ull*)nullptr, accP);

#pragma unroll
        for (int o = 4; o < OUTC; o++) {
            float be = s_b[o];
            float a, bb;
            upk(accP[(o - 4) * 2], a, bb);
            g_sigma[(o * 4 + 0) * NTOK + tok] = softplus(a + be);
            g_sigma[(o * 4 + 1) * NTOK + tok] = softplus(bb + be);
            upk(accP[(o - 4) * 2 + 1], a, bb);
            g_sigma[(o * 4 + 2) * NTOK + tok] = softplus(a + be);
            g_sigma[(o * 4 + 3) * NTOK + tok] = softplus(bb + be);
        }
    }
}

// ---------------------------------------------------------------------------
// Kernel 2: batched 8x8 symmetric eigh, fixed-sweep cyclic Jacobi.
// (R5 version verbatim — best measured eigh at 48.2 us.)
// ---------------------------------------------------------------------------
#define TI(i,j) ((i) <= (j) ? ((i)*(17-(i)))/2 + ((j)-(i)) \
                            : ((j)*(17-(j)))/2 + ((i)-(j)))
#define AT(i,j) Au[TI(i,j)]

__global__ void __launch_bounds__(128) eigh_kernel(float* __restrict__ out_pd)
{
    const int tok = blockIdx.x * 128 + threadIdx.x;

    float Au[HALF];
#pragma unroll
    for (int e = 0; e < HALF; e++) Au[e] = g_sigma[(size_t)e * NTOK + tok];

    // V packed as row-pairs: Vp[col][jp] = ( V[2jp][col], V[2jp+1][col] )
    ull Vp[8][4];
#pragma unroll
    for (int c = 0; c < 8; c++)
#pragma unroll
        for (int jp = 0; jp < 4; jp++)
            Vp[c][jp] = pk((2 * jp == c) ? 1.0f : 0.0f,
                           (2 * jp + 1 == c) ? 1.0f : 0.0f);

#pragma unroll 1
    for (int sweep = 0; sweep < NSWEEP; sweep++) {
#pragma unroll
        for (int p = 0; p < 7; p++) {
#pragma unroll
            for (int q = p + 1; q < 8; q++) {
                float apq = AT(p, q);
                float app = AT(p, p);
                float aqq = AT(q, q);
                float tau = (aqq - app);
                tau += copysignf(1e-18f, tau);          // degenerate-safe
                float r2    = fmaf(tau, tau, 4.0f * apq * apq);
                float inv_r = rsqrtf(r2);
                float c2    = fmaf(0.5f * fabsf(tau), inv_r, 0.5f); // cos^2
                float cinv  = rsqrtf(c2);
                float cc    = c2 * cinv;                            // cos
                float st    = (tau < 0.0f) ? -apq : apq;            // sign(tau)*apq
                float ss    = st * inv_r * cinv;                    // sin
                float s2c   = 2.0f * st * inv_r;                    // sin(2phi) fold

                float napp = c2 * app + (1.0f - c2) * aqq - s2c * apq;
                AT(p, p) = napp;
                AT(q, q) = (app + aqq) - napp;
                AT(p, q) = 0.0f;

#pragma unroll
                for (int j = 0; j < 8; j++) {
                    if (j == p || j == q) continue;
                    float ajp = AT(j, p), ajq = AT(j, q);
                    AT(j, p) = cc * ajp - ss * ajq;
                    AT(j, q) = ss * ajp + cc * ajq;
                }

                // packed V column rotation
                ull cc2  = pk(cc, cc);
                ull ss2  = pk(ss, ss);
                ull nss2 = pk(-ss, -ss);
#pragma unroll
                for (int jp = 0; jp < 4; jp++) {
                    ull vp = Vp[p][jp], vq = Vp[q][jp];
                    Vp[p][jp] = fma2(nss2, vq, mul2(cc2, vp));
                    Vp[q][jp] = fma2(cc2,  vq, mul2(ss2, vp));
                }
            }
        }
    }

    float V[8][8];   // V[row][col]
#pragma unroll
    for (int c = 0; c < 8; c++)
#pragma unroll
        for (int jp = 0; jp < 4; jp++)
            upk(Vp[c][jp], V[2 * jp][c], V[2 * jp + 1][c]);

    float lam[8];
#pragma unroll
    for (int k = 0; k < 8; k++) lam[k] = fmaxf(AT(k, k), MIN_EIG);

    float W[8][8];
#pragma unroll
    for (int i = 0; i < 8; i++)
#pragma unroll
        for (int k = 0; k < 8; k++) W[i][k] = V[i][k] * lam[k];

    float pd[8][8];
#pragma unroll
    for (int i = 0; i < 8; i++) {
#pragma unroll
        for (int j = i; j < 8; j++) {
            float acc = 0.0f;
#pragma unroll
            for (int k = 0; k < 8; k++) acc = fmaf(W[i][k], V[j][k], acc);
            pd[i][j] = acc; pd[j][i] = acc;
        }
    }

    float* o = out_pd + (size_t)tok * 64;
#pragma unroll
    for (int i = 0; i < 8; i++) {
        ((float4*)o)[i * 2]     = make_float4(pd[i][0], pd[i][1], pd[i][2], pd[i][3]);
        ((float4*)o)[i * 2 + 1] = make_float4(pd[i][4], pd[i][5], pd[i][6], pd[i][7]);
    }
}

// ---------------------------------------------------------------------------
extern "C" void kernel_launch(void* const* d_in, const int* in_sizes, int n_in,
                              void* d_out, int out_size)
{
    // Identify inputs by element count (robust to metadata ordering):
    // x: 67108864, w_n: 64, b_n: 1, w_p: 2880, b_p: 9
    const float* x  = nullptr;
    const float* wn = nullptr;
    const float* bn = nullptr;
    const float* wp = nullptr;
    const float* bp = nullptr;
    for (int i = 0; i < n_in; i++) {
        switch (in_sizes[i]) {
            case 64:    wn = (const float*)d_in[i]; break;
            case 1:     bn = (const float*)d_in[i]; break;
            case 2880:  wp = (const float*)d_in[i]; break;
            case 9:     bp = (const float*)d_in[i]; break;
            default:    x  = (const float*)d_in[i]; break;
        }
    }

    float* out = (float*)d_out;
    float* loc = out;                                            // [B,1,H,FD]
    float* pd  = out + ((size_t)out_size - (size_t)NTOK * 64);   // [B,1,H,8,8]

    conv_kernel<<<NTOK / 128, 256>>>(x, wn, bn, wp, bp, loc);
    eigh_kernel<<<NTOK / 128, 128>>>(pd);
}